// round 11
// baseline (speedup 1.0000x reference)
#include <cuda_runtime.h>
#include <cuda_bf16.h>
#include <cstdint>

// BundleAdjustmentModel: project N points into V=64 camera views.
// out[v][n] = (u,v);  cam = R_v p + t_v;  u = -f*x/sz + cx, v = f*y/sz + cy.
// HBM-write-bound (256 MB out). Single persistent-wave kernel:
//   - 8 view-groups (VG=8 views each) x P=296 blocks = 2368 = one resident
//     wave at 16 CTAs/SM. __launch_bounds__(128,16) forces <=32 regs so 16
//     CTAs actually fit (R10: 35 regs -> 40 alloc -> 12 CTAs/SM -> 59% occ).
//   - each block computes its 8 views' folded params ONCE, then grid-strides
//     over point chunks (prologue amortized ~7x).
//   - mainloop: 2 points/thread, ONE warp-contiguous STG.128 per view
//     (512B burst). Warp store contiguity is load-bearing (R7).
// Folding:  A = -f*R0, tA = -f*tx ; B = f*R1, tB = f*ty ; C = R2, tC = -depth
// safe-z via clamp: 1/safe_z == clamp(1/z, -1/eps, +1/eps)

#define V_VIEWS 64
#define VG 8            // views per block

__global__ __launch_bounds__(128, 16)
void bundle_project_kernel(const float* __restrict__ points,     // [N,3]
                           const float* __restrict__ euler,      // [V,3]
                           const float* __restrict__ txy,        // [V,2]
                           const float* __restrict__ tdepth,     // [V]
                           const float* __restrict__ focal_raw,  // [1]
                           const int*   __restrict__ cx_p,
                           const int*   __restrict__ cy_p,
                           float* __restrict__ out,              // [V,N,2]
                           int n_pts,
                           int chunks,
                           int P)        // blocks per view-group
{
    // 12 floats/view, 48B rows (16B-aligned) -> 3x LDS.128 broadcast per view.
    // layout: [Ax Ay Az Bx][By Bz Cx Cy][Cz tA tB tC]
    __shared__ __align__(16) float sP[VG][12];
    __shared__ float s_cx, s_cy;

    const int tid   = threadIdx.x;
    const int vbase = (blockIdx.x / P) * VG;
    const int c0    = blockIdx.x % P;

    if (tid < VG) {
        const int v = vbase + tid;
        const float f = log1pf(expf(focal_raw[0])) + 50.0f;
        const float ex = euler[v * 3 + 0];
        const float ey = euler[v * 3 + 1];
        const float ez = euler[v * 3 + 2];
        float cxa = cosf(ex), sxa = sinf(ex);
        float cya = cosf(ey), sya = sinf(ey);
        float cza = cosf(ez), sza = sinf(ez);
        // R = Rx * Ry * Rz
        float R00 = cya * cza,                   R01 = -cya * sza,                  R02 = sya;
        float R10 = cxa * sza + sxa * sya * cza, R11 = cxa * cza - sxa * sya * sza, R12 = -sxa * cya;
        float R20 = sxa * sza - cxa * sya * cza, R21 = sxa * cza + cxa * sya * sza, R22 = cxa * cya;

        sP[tid][0] = -f * R00;  sP[tid][1] = -f * R01;  sP[tid][2] = -f * R02;
        sP[tid][3] =  f * R10;  sP[tid][4] =  f * R11;  sP[tid][5] =  f * R12;
        sP[tid][6] =  R20;      sP[tid][7] =  R21;      sP[tid][8] =  R22;
        sP[tid][9]  = -f * txy[v * 2 + 0];                  // tA
        sP[tid][10] =  f * txy[v * 2 + 1];                  // tB
        const float d = tdepth[v];
        sP[tid][11] = -(log1pf(expf(d)) + 0.25f);           // tC = -depth
    }
    if (tid == 0) {
        s_cx = (float)cx_p[0];
        s_cy = (float)cy_p[0];
    }
    __syncthreads();

    const float cxf = s_cx;
    const float cyf = s_cy;
    const float INV_CLAMP = 1.0f / 1e-4f;          // 1/Z_EPS
    const size_t view_stride = (size_t)n_pts * 2;  // floats per view slab

    for (int chunk = c0; chunk < chunks; chunk += P) {
        const int i  = chunk * 128 + tid;
        const int n0 = 2 * i;
        if (n0 >= n_pts) break;                    // later chunks only larger
        const bool has2 = (n0 + 1) < n_pts;

        const float p0x = points[(size_t)n0 * 3 + 0];
        const float p0y = points[(size_t)n0 * 3 + 1];
        const float p0z = points[(size_t)n0 * 3 + 2];
        float p1x = 0.f, p1y = 0.f, p1z = 0.f;
        if (has2) {
            p1x = points[(size_t)(n0 + 1) * 3 + 0];
            p1y = points[(size_t)(n0 + 1) * 3 + 1];
            p1z = points[(size_t)(n0 + 1) * 3 + 2];
        }

        float* base = out + ((size_t)vbase * n_pts + n0) * 2;

        #pragma unroll
        for (int v = 0; v < VG; v++) {
            const float4* pr = reinterpret_cast<const float4*>(&sP[v][0]);
            const float4 r0 = pr[0];   // Ax Ay Az Bx
            const float4 r1 = pr[1];   // By Bz Cx Cy
            const float4 r2 = pr[2];   // Cz tA tB tC

            // point 0
            float a0 = fmaf(r0.x, p0x, fmaf(r0.y, p0y, fmaf(r0.z, p0z, r2.y)));
            float b0 = fmaf(r0.w, p0x, fmaf(r1.x, p0y, fmaf(r1.y, p0z, r2.z)));
            float z0 = fmaf(r1.z, p0x, fmaf(r1.w, p0y, fmaf(r2.x, p0z, r2.w)));
            float inv0 = __fdividef(1.0f, z0);
            inv0 = fminf(fmaxf(inv0, -INV_CLAMP), INV_CLAMP);
            float u0 = fmaf(a0, inv0, cxf);
            float w0 = fmaf(b0, inv0, cyf);

            // point 1
            float a1 = fmaf(r0.x, p1x, fmaf(r0.y, p1y, fmaf(r0.z, p1z, r2.y)));
            float b1 = fmaf(r0.w, p1x, fmaf(r1.x, p1y, fmaf(r1.y, p1z, r2.z)));
            float z1 = fmaf(r1.z, p1x, fmaf(r1.w, p1y, fmaf(r2.x, p1z, r2.w)));
            float inv1 = __fdividef(1.0f, z1);
            inv1 = fminf(fmaxf(inv1, -INV_CLAMP), INV_CLAMP);
            float u1 = fmaf(a1, inv1, cxf);
            float w1 = fmaf(b1, inv1, cyf);

            if (has2) {
                __stcs(reinterpret_cast<float4*>(base), make_float4(u0, w0, u1, w1));
            } else {
                __stcs(reinterpret_cast<float2*>(base), make_float2(u0, w0));
            }
            base += view_stride;
        }
    }
}

extern "C" void kernel_launch(void* const* d_in, const int* in_sizes, int n_in,
                              void* d_out, int out_size) {
    const float* points    = (const float*)d_in[0];
    const float* euler     = (const float*)d_in[1];
    const float* txy       = (const float*)d_in[2];
    const float* tdepth    = (const float*)d_in[3];
    const float* focal_raw = (const float*)d_in[4];
    const int*   cx_p      = (const int*)d_in[5];
    const int*   cy_p      = (const int*)d_in[6];
    float*       out       = (float*)d_out;

    const int n_pts = in_sizes[0] / 3;       // points is [N,3]
    const int pairs = (n_pts + 1) / 2;       // 2 points per thread
    const int threads = 128;
    const int chunks = (pairs + threads - 1) / threads;

    // One resident wave: 148 SMs x 16 CTAs(128thr, <=32regs) = 2368 blocks
    int P = 296;
    if (P > chunks) P = chunks;
    const int blocks = P * (V_VIEWS / VG);

    bundle_project_kernel<<<blocks, threads>>>(points, euler, txy, tdepth,
                                               focal_raw, cx_p, cy_p,
                                               out, n_pts, chunks, P);
}

// round 13
// speedup vs baseline: 1.1397x; 1.1397x over previous
#include <cuda_runtime.h>
#include <cuda_bf16.h>
#include <cstdint>

// BundleAdjustmentModel: project N points into V=64 camera views.
// out[v][n] = (u,v);  cam = R_v p + t_v;  u = -f*x/sz + cx, v = f*y/sz + cy.
// HBM-write-bound (256 MB out). R5 shape (many small blocks, dynamic
// balancing), prologue count halved via 256-thread blocks:
//   - 256-thread blocks, VG=8 views per block, 2 points per thread.
//   - grid = chunks x 8 view-groups (1D-decomposed) = 7816 blocks.
//   - mainloop: ONE warp-contiguous STG.128 per view (512B burst per warp).
//     Warp store contiguity is load-bearing (R7).
//   - prologue math must be EXACT (sincosf/log1pf/expf): R12 showed fast-math
//     trig perturbs R by ~4e-7, which near |z|~Z_EPS amplifies through 1/z
//     into ~1e-2 output error. Do not fast-math the rotation setup.
// Folding:  A = -f*R0, tA = -f*tx ; B = f*R1, tB = f*ty ; C = R2, tC = -depth
// safe-z via clamp: 1/safe_z == clamp(1/z, -1/eps, +1/eps)

#define V_VIEWS 64
#define VG 8            // views per block
#define TPB 256

__global__ __launch_bounds__(TPB, 8)
void bundle_project_kernel(const float* __restrict__ points,     // [N,3]
                           const float* __restrict__ euler,      // [V,3]
                           const float* __restrict__ txy,        // [V,2]
                           const float* __restrict__ tdepth,     // [V]
                           const float* __restrict__ focal_raw,  // [1]
                           const int*   __restrict__ cx_p,
                           const int*   __restrict__ cy_p,
                           float* __restrict__ out,              // [V,N,2]
                           int n_pts,
                           int chunks)
{
    // 12 floats/view, 48B rows (16B-aligned) -> 3x LDS.128 broadcast per view.
    // layout: [Ax Ay Az Bx][By Bz Cx Cy][Cz tA tB tC]
    __shared__ __align__(16) float sP[VG][12];
    __shared__ float s_cx, s_cy;

    const int tid   = threadIdx.x;
    const int chunk = blockIdx.x % chunks;
    const int vbase = (blockIdx.x / chunks) * VG;

    if (tid < VG) {
        const int v = vbase + tid;
        const float f = log1pf(expf(focal_raw[0])) + 50.0f;
        const float ex = euler[v * 3 + 0];
        const float ey = euler[v * 3 + 1];
        const float ez = euler[v * 3 + 2];
        float cxa = cosf(ex), sxa = sinf(ex);
        float cya = cosf(ey), sya = sinf(ey);
        float cza = cosf(ez), sza = sinf(ez);
        // R = Rx * Ry * Rz
        float R00 = cya * cza,                   R01 = -cya * sza,                  R02 = sya;
        float R10 = cxa * sza + sxa * sya * cza, R11 = cxa * cza - sxa * sya * sza, R12 = -sxa * cya;
        float R20 = sxa * sza - cxa * sya * cza, R21 = sxa * cza + cxa * sya * sza, R22 = cxa * cya;

        sP[tid][0] = -f * R00;  sP[tid][1] = -f * R01;  sP[tid][2] = -f * R02;
        sP[tid][3] =  f * R10;  sP[tid][4] =  f * R11;  sP[tid][5] =  f * R12;
        sP[tid][6] =  R20;      sP[tid][7] =  R21;      sP[tid][8] =  R22;
        sP[tid][9]  = -f * txy[v * 2 + 0];                  // tA
        sP[tid][10] =  f * txy[v * 2 + 1];                  // tB
        const float d = tdepth[v];
        sP[tid][11] = -(log1pf(expf(d)) + 0.25f);           // tC = -depth
    }
    if (tid == 0) {
        s_cx = (float)cx_p[0];
        s_cy = (float)cy_p[0];
    }
    __syncthreads();

    const int i  = chunk * TPB + tid;
    const int n0 = 2 * i;
    if (n0 >= n_pts) return;
    const bool has2 = (n0 + 1) < n_pts;

    const float p0x = points[(size_t)n0 * 3 + 0];
    const float p0y = points[(size_t)n0 * 3 + 1];
    const float p0z = points[(size_t)n0 * 3 + 2];
    float p1x = 0.f, p1y = 0.f, p1z = 0.f;
    if (has2) {
        p1x = points[(size_t)(n0 + 1) * 3 + 0];
        p1y = points[(size_t)(n0 + 1) * 3 + 1];
        p1z = points[(size_t)(n0 + 1) * 3 + 2];
    }

    const float cxf = s_cx;
    const float cyf = s_cy;
    const float INV_CLAMP = 1.0f / 1e-4f;          // 1/Z_EPS
    const size_t view_stride = (size_t)n_pts * 2;  // floats per view slab

    float* base = out + ((size_t)vbase * n_pts + n0) * 2;

    #pragma unroll
    for (int v = 0; v < VG; v++) {
        const float4* pr = reinterpret_cast<const float4*>(&sP[v][0]);
        const float4 r0 = pr[0];   // Ax Ay Az Bx
        const float4 r1 = pr[1];   // By Bz Cx Cy
        const float4 r2 = pr[2];   // Cz tA tB tC

        // point 0
        float a0 = fmaf(r0.x, p0x, fmaf(r0.y, p0y, fmaf(r0.z, p0z, r2.y)));
        float b0 = fmaf(r0.w, p0x, fmaf(r1.x, p0y, fmaf(r1.y, p0z, r2.z)));
        float z0 = fmaf(r1.z, p0x, fmaf(r1.w, p0y, fmaf(r2.x, p0z, r2.w)));
        float inv0 = __fdividef(1.0f, z0);
        inv0 = fminf(fmaxf(inv0, -INV_CLAMP), INV_CLAMP);
        float u0 = fmaf(a0, inv0, cxf);
        float w0 = fmaf(b0, inv0, cyf);

        // point 1
        float a1 = fmaf(r0.x, p1x, fmaf(r0.y, p1y, fmaf(r0.z, p1z, r2.y)));
        float b1 = fmaf(r0.w, p1x, fmaf(r1.x, p1y, fmaf(r1.y, p1z, r2.z)));
        float z1 = fmaf(r1.z, p1x, fmaf(r1.w, p1y, fmaf(r2.x, p1z, r2.w)));
        float inv1 = __fdividef(1.0f, z1);
        inv1 = fminf(fmaxf(inv1, -INV_CLAMP), INV_CLAMP);
        float u1 = fmaf(a1, inv1, cxf);
        float w1 = fmaf(b1, inv1, cyf);

        if (has2) {
            __stcs(reinterpret_cast<float4*>(base), make_float4(u0, w0, u1, w1));
        } else {
            __stcs(reinterpret_cast<float2*>(base), make_float2(u0, w0));
        }
        base += view_stride;
    }
}

extern "C" void kernel_launch(void* const* d_in, const int* in_sizes, int n_in,
                              void* d_out, int out_size) {
    const float* points    = (const float*)d_in[0];
    const float* euler     = (const float*)d_in[1];
    const float* txy       = (const float*)d_in[2];
    const float* tdepth    = (const float*)d_in[3];
    const float* focal_raw = (const float*)d_in[4];
    const int*   cx_p      = (const int*)d_in[5];
    const int*   cy_p      = (const int*)d_in[6];
    float*       out       = (float*)d_out;

    const int n_pts = in_sizes[0] / 3;       // points is [N,3]
    const int pairs = (n_pts + 1) / 2;       // 2 points per thread
    const int chunks = (pairs + TPB - 1) / TPB;
    const int blocks = chunks * (V_VIEWS / VG);

    bundle_project_kernel<<<blocks, TPB>>>(points, euler, txy, tdepth,
                                           focal_raw, cx_p, cy_p,
                                           out, n_pts, chunks);
}